// round 4
// baseline (speedup 1.0000x reference)
#include <cuda_runtime.h>
#include <math.h>

// Problem constants
#define B_    16
#define C_    64
#define H_    224
#define W_    224
#define HW_   (H_ * W_)          // 50176
#define CHW_  (C_ * HW_)         // 3211264
#define HW4_  (HW_ / 4)          // 12544
#define CHW4_ (CHW_ / 4)         // 802816

#define BAND   8                 // output rows per CTA
#define SR     14                // smem feat rows = BAND + 6 (halo)
#define SCOLS  232               // smem row stride; data cols 4..227, zero pads 0..3 / 228..231
#define FEATN  (SR * SCOLS)      // floats per channel plane
#define NTHR   448               // 8 rows x 56 float4 positions
#define SMEM_FORCE_BYTES (130 * 1024)   // > 114KB -> exactly 1 CTA/SM (occupancy throttle)

// ---------------------------------------------------------------------------
// Single fused kernel. One CTA = (batch, 8-row band).
//  Phase 1: reduce band+halo rows (14 x 224) over 64 channels -> smem feat.
//           (halo rows are also reduced by neighbor CTAs; concurrent in-wave
//            CTAs share those x reads via L2)
//  Phase 2: 7x7 conv + bias + sigmoid -> per-thread float4 gate (registers).
//  Phase 3: re-read own band's x (L2-resident from phase 1), multiply, store.
// L2 footprint per wave: 148 CTAs x 802 KB = 119 MB < 126 MB L2.
// ---------------------------------------------------------------------------
__global__ void __launch_bounds__(NTHR) fused_all_kernel(
        const float* __restrict__ x,
        const float* __restrict__ conv_w,
        const float* __restrict__ conv_b,
        float* __restrict__ out) {
    extern __shared__ float smem[];          // dynamic (oversized on purpose)
    float* s_avg = smem;                     // FEATN floats
    float* s_max = smem + FEATN;             // FEATN floats
    __shared__ float s_w[98];

    int t  = threadIdx.x;                    // 0..447
    int b  = blockIdx.x;                     // 16 batches (fast dim -> in-wave batches)
    int h0 = blockIdx.y * BAND;              // 28 bands

    if (t < 98) s_w[t] = conv_w[t];

    // Zero the horizontal edge pads (cols 0..3 and 228..231 of every row/ch)
    if (t < 56) {
        int side  = t & 1;
        int combo = t >> 1;                  // 0..27 = (row, ch)
        int r  = combo % SR;
        int ch = combo / SR;
        float* p = (ch ? s_max : s_avg) + r * SCOLS + (side ? 228 : 0);
        *(float4*)p = make_float4(0.f, 0.f, 0.f, 0.f);
    }

    const float4* x4 = (const float4*)x;

    // ---- Phase 1: channel reduce of 14 x 56 float4 positions ----
    for (int p = t; p < SR * 56; p += NTHR) {
        int r  = p / 56;                     // smem row 0..13
        int w4 = p - r * 56;                 // float4 col 0..55
        int gh = h0 + r - 3;                 // global row (may be out of image)

        float4 s = make_float4(0.f, 0.f, 0.f, 0.f);
        float4 m = s;                        // zero-padding semantics for OOB rows
        if (gh >= 0 && gh < H_) {
            m = make_float4(-INFINITY, -INFINITY, -INFINITY, -INFINITY);
            long base = (long)b * CHW4_ + gh * 56 + w4;
#pragma unroll 8
            for (int c = 0; c < C_; c++) {
                float4 v = x4[base + (long)c * HW4_];
                s.x += v.x; s.y += v.y; s.z += v.z; s.w += v.w;
                m.x = fmaxf(m.x, v.x); m.y = fmaxf(m.y, v.y);
                m.z = fmaxf(m.z, v.z); m.w = fmaxf(m.w, v.w);
            }
            const float inv = 1.0f / (float)C_;
            s.x *= inv; s.y *= inv; s.z *= inv; s.w *= inv;
        }
        int cc = 4 + 4 * w4;                 // 16B-aligned smem col
        *(float4*)(s_avg + r * SCOLS + cc) = s;
        *(float4*)(s_max + r * SCOLS + cc) = m;
    }
    __syncthreads();

    // ---- Phase 2: 7x7 conv + sigmoid for this thread's own position ----
    int rb = t / 56;                         // band row 0..7
    int w4 = t - rb * 56;                    // float4 col 0..55
    float bias = conv_b[0];
    float a0 = bias, a1 = bias, a2 = bias, a3 = bias;

#pragma unroll
    for (int ch = 0; ch < 2; ch++) {
        const float* f = ch ? s_max : s_avg;
#pragma unroll
        for (int kh = 0; kh < 7; kh++) {
            // window rows: smem rows rb..rb+6 ; cols 4*w4 .. 4*w4+11
            const float* rp = f + (rb + kh) * SCOLS + 4 * w4;
            float4 A = *(const float4*)(rp);
            float4 Bv = *(const float4*)(rp + 4);
            float4 Cv = *(const float4*)(rp + 8);
            float r_[12] = { A.x, A.y, A.z, A.w,
                             Bv.x, Bv.y, Bv.z, Bv.w,
                             Cv.x, Cv.y, Cv.z, Cv.w };
            const float* wk = s_w + ch * 49 + kh * 7;
#pragma unroll
            for (int kw = 0; kw < 7; kw++) {
                float wv = wk[kw];
                a0 = fmaf(r_[kw + 1], wv, a0);
                a1 = fmaf(r_[kw + 2], wv, a1);
                a2 = fmaf(r_[kw + 3], wv, a2);
                a3 = fmaf(r_[kw + 4], wv, a3);
            }
        }
    }

    float4 g;
    g.x = 1.0f / (1.0f + __expf(-a0));
    g.y = 1.0f / (1.0f + __expf(-a1));
    g.z = 1.0f / (1.0f + __expf(-a2));
    g.w = 1.0f / (1.0f + __expf(-a3));

    // ---- Phase 3: multiply own band across 64 channels (L2-resident x) ----
    long base = (long)b * CHW4_ + (h0 + rb) * 56 + w4;
    float4* o4 = (float4*)out;
#pragma unroll 8
    for (int c = 0; c < C_; c++) {
        long idx = base + (long)c * HW4_;
        float4 v = x4[idx];
        v.x *= g.x; v.y *= g.y; v.z *= g.z; v.w *= g.w;
        __stcs(o4 + idx, v);
    }
}

// ---------------------------------------------------------------------------
extern "C" void kernel_launch(void* const* d_in, const int* in_sizes, int n_in,
                              void* d_out, int out_size) {
    const float* x      = (const float*)d_in[0];
    const float* conv_w = (const float*)d_in[1];
    const float* conv_b = (const float*)d_in[2];
    float* out = (float*)d_out;

    // Raise the dynamic-smem cap; oversized request throttles to 1 CTA/SM so a
    // full wave's read footprint (148 x 802KB = 119MB) stays L2-resident.
    // (Host function state, not an allocation, not a stream op; idempotent.)
    cudaFuncSetAttribute(fused_all_kernel,
                         cudaFuncAttributeMaxDynamicSharedMemorySize,
                         SMEM_FORCE_BYTES);

    dim3 grd(B_, H_ / BAND);                 // (16, 28) = 448 CTAs, ~3 waves
    fused_all_kernel<<<grd, NTHR, SMEM_FORCE_BYTES>>>(x, conv_w, conv_b, out);
}

// round 5
// speedup vs baseline: 1.0015x; 1.0015x over previous
#include <cuda_runtime.h>
#include <math.h>

// Problem constants
#define B_    16
#define C_    64
#define H_    224
#define W_    224
#define HW_   (H_ * W_)          // 50176
#define CHW_  (C_ * HW_)         // 3211264
#define HW4_  (HW_ / 4)          // 12544
#define CHW4_ (CHW_ / 4)         // 802816

#define BAND   8                 // output rows per CTA
#define SR     14                // smem feat rows = BAND + 6 (halo)
#define SCOLS  232               // smem row stride; data cols 4..227, zero pads 0..3 / 228..231
#define FEATN  (SR * SCOLS)      // floats per channel plane
#define NTHR   448               // 8 rows x 56 float4 positions
#define SMEM_FORCE_BYTES (130 * 1024)   // > 114KB -> exactly 1 CTA/SM (occupancy throttle)

// ---------------------------------------------------------------------------
// Single fused kernel. One CTA = (batch, 8-row band).
//  Phase 1: reduce band+halo rows (14 x 224) over 64 channels -> smem feat.
//           (halo rows are also reduced by neighbor CTAs; concurrent in-wave
//            CTAs share those x reads via L2)
//  Phase 2: 7x7 conv + bias + sigmoid -> per-thread float4 gate (registers).
//  Phase 3: re-read own band's x (L2-resident from phase 1), multiply, store.
// L2 footprint per wave: 148 CTAs x 802 KB = 119 MB < 126 MB L2.
// ---------------------------------------------------------------------------
__global__ void __launch_bounds__(NTHR) fused_all_kernel(
        const float* __restrict__ x,
        const float* __restrict__ conv_w,
        const float* __restrict__ conv_b,
        float* __restrict__ out) {
    extern __shared__ float smem[];          // dynamic (oversized on purpose)
    float* s_avg = smem;                     // FEATN floats
    float* s_max = smem + FEATN;             // FEATN floats
    __shared__ float s_w[98];

    int t  = threadIdx.x;                    // 0..447
    int b  = blockIdx.x;                     // 16 batches (fast dim -> in-wave batches)
    int h0 = blockIdx.y * BAND;              // 28 bands

    if (t < 98) s_w[t] = conv_w[t];

    // Zero the horizontal edge pads (cols 0..3 and 228..231 of every row/ch)
    if (t < 56) {
        int side  = t & 1;
        int combo = t >> 1;                  // 0..27 = (row, ch)
        int r  = combo % SR;
        int ch = combo / SR;
        float* p = (ch ? s_max : s_avg) + r * SCOLS + (side ? 228 : 0);
        *(float4*)p = make_float4(0.f, 0.f, 0.f, 0.f);
    }

    const float4* x4 = (const float4*)x;

    // ---- Phase 1: channel reduce of 14 x 56 float4 positions ----
    for (int p = t; p < SR * 56; p += NTHR) {
        int r  = p / 56;                     // smem row 0..13
        int w4 = p - r * 56;                 // float4 col 0..55
        int gh = h0 + r - 3;                 // global row (may be out of image)

        float4 s = make_float4(0.f, 0.f, 0.f, 0.f);
        float4 m = s;                        // zero-padding semantics for OOB rows
        if (gh >= 0 && gh < H_) {
            m = make_float4(-INFINITY, -INFINITY, -INFINITY, -INFINITY);
            long base = (long)b * CHW4_ + gh * 56 + w4;
#pragma unroll 8
            for (int c = 0; c < C_; c++) {
                float4 v = x4[base + (long)c * HW4_];
                s.x += v.x; s.y += v.y; s.z += v.z; s.w += v.w;
                m.x = fmaxf(m.x, v.x); m.y = fmaxf(m.y, v.y);
                m.z = fmaxf(m.z, v.z); m.w = fmaxf(m.w, v.w);
            }
            const float inv = 1.0f / (float)C_;
            s.x *= inv; s.y *= inv; s.z *= inv; s.w *= inv;
        }
        int cc = 4 + 4 * w4;                 // 16B-aligned smem col
        *(float4*)(s_avg + r * SCOLS + cc) = s;
        *(float4*)(s_max + r * SCOLS + cc) = m;
    }
    __syncthreads();

    // ---- Phase 2: 7x7 conv + sigmoid for this thread's own position ----
    int rb = t / 56;                         // band row 0..7
    int w4 = t - rb * 56;                    // float4 col 0..55
    float bias = conv_b[0];
    float a0 = bias, a1 = bias, a2 = bias, a3 = bias;

#pragma unroll
    for (int ch = 0; ch < 2; ch++) {
        const float* f = ch ? s_max : s_avg;
#pragma unroll
        for (int kh = 0; kh < 7; kh++) {
            // window rows: smem rows rb..rb+6 ; cols 4*w4 .. 4*w4+11
            const float* rp = f + (rb + kh) * SCOLS + 4 * w4;
            float4 A = *(const float4*)(rp);
            float4 Bv = *(const float4*)(rp + 4);
            float4 Cv = *(const float4*)(rp + 8);
            float r_[12] = { A.x, A.y, A.z, A.w,
                             Bv.x, Bv.y, Bv.z, Bv.w,
                             Cv.x, Cv.y, Cv.z, Cv.w };
            const float* wk = s_w + ch * 49 + kh * 7;
#pragma unroll
            for (int kw = 0; kw < 7; kw++) {
                float wv = wk[kw];
                a0 = fmaf(r_[kw + 1], wv, a0);
                a1 = fmaf(r_[kw + 2], wv, a1);
                a2 = fmaf(r_[kw + 3], wv, a2);
                a3 = fmaf(r_[kw + 4], wv, a3);
            }
        }
    }

    float4 g;
    g.x = 1.0f / (1.0f + __expf(-a0));
    g.y = 1.0f / (1.0f + __expf(-a1));
    g.z = 1.0f / (1.0f + __expf(-a2));
    g.w = 1.0f / (1.0f + __expf(-a3));

    // ---- Phase 3: multiply own band across 64 channels (L2-resident x) ----
    long base = (long)b * CHW4_ + (h0 + rb) * 56 + w4;
    float4* o4 = (float4*)out;
#pragma unroll 8
    for (int c = 0; c < C_; c++) {
        long idx = base + (long)c * HW4_;
        float4 v = x4[idx];
        v.x *= g.x; v.y *= g.y; v.z *= g.z; v.w *= g.w;
        __stcs(o4 + idx, v);
    }
}

// ---------------------------------------------------------------------------
extern "C" void kernel_launch(void* const* d_in, const int* in_sizes, int n_in,
                              void* d_out, int out_size) {
    const float* x      = (const float*)d_in[0];
    const float* conv_w = (const float*)d_in[1];
    const float* conv_b = (const float*)d_in[2];
    float* out = (float*)d_out;

    // Raise the dynamic-smem cap; oversized request throttles to 1 CTA/SM so a
    // full wave's read footprint (148 x 802KB = 119MB) stays L2-resident.
    // (Host function state, not an allocation, not a stream op; idempotent.)
    cudaFuncSetAttribute(fused_all_kernel,
                         cudaFuncAttributeMaxDynamicSharedMemorySize,
                         SMEM_FORCE_BYTES);

    dim3 grd(B_, H_ / BAND);                 // (16, 28) = 448 CTAs, ~3 waves
    fused_all_kernel<<<grd, NTHR, SMEM_FORCE_BYTES>>>(x, conv_w, conv_b, out);
}

// round 6
// speedup vs baseline: 1.5813x; 1.5789x over previous
#include <cuda_runtime.h>
#include <math.h>

// Problem constants
#define B_    16
#define C_    64
#define H_    224
#define W_    224
#define HW_   (H_ * W_)          // 50176
#define CHW_  (C_ * HW_)         // 3211264
#define HW4_  (HW_ / 4)          // 12544
#define CHW4_ (CHW_ / 4)         // 802816
#define TOTAL4 (B_ * CHW4_)      // 12845056

// Scratch (device globals — no allocation allowed)
__device__ float g_avg[B_ * HW_];   // 3.2 MB
__device__ float g_max[B_ * HW_];   // 3.2 MB
__device__ float g_gate[B_ * HW_];  // 3.2 MB (post-sigmoid)

// ---------------------------------------------------------------------------
// Kernel 1: channel-wise mean + max reduce (proven: 33.3us, 79.5% DRAM).
// One thread = 4 consecutive w positions; 64 channel-strided LDG.128.
// ---------------------------------------------------------------------------
__global__ void reduce_kernel(const float* __restrict__ x) {
    int idx = blockIdx.x * blockDim.x + threadIdx.x;   // float4 idx in [0, B_*HW4_)
    if (idx >= B_ * HW4_) return;
    int b = idx / HW4_;
    int p = idx - b * HW4_;

    const float4* x4 = (const float4*)x;
    long base = (long)b * CHW4_ + p;

    float4 s = make_float4(0.f, 0.f, 0.f, 0.f);
    float4 m = make_float4(-INFINITY, -INFINITY, -INFINITY, -INFINITY);

#pragma unroll 8
    for (int c = 0; c < C_; c++) {
        float4 v = x4[base + (long)c * HW4_];
        s.x += v.x; s.y += v.y; s.z += v.z; s.w += v.w;
        m.x = fmaxf(m.x, v.x); m.y = fmaxf(m.y, v.y);
        m.z = fmaxf(m.z, v.z); m.w = fmaxf(m.w, v.w);
    }
    const float inv = 1.0f / (float)C_;
    s.x *= inv; s.y *= inv; s.z *= inv; s.w *= inv;

    __stcs(((float4*)g_avg) + idx, s);
    __stcs(((float4*)g_max) + idx, m);
}

// ---------------------------------------------------------------------------
// Kernel 2: 7x7 conv (2ch -> 1ch, pad 3) + bias + sigmoid -> gate.
// Block (28,8) = 224 thr; tile 112x8 (4 outputs/thread along w).
// Halo 2 x 14 x 118 in smem (row stride 120 -> aligned LDS.128).
// Traffic ~12MB of L2 across 896 CTAs -> target <= 3us.
// ---------------------------------------------------------------------------
#define CTW  112
#define CTH  8
#define HTW  118          // CTW + 6
#define HTH  14           // CTH + 6
#define HTWP 120          // padded row stride

__global__ void __launch_bounds__(224) conv_sigmoid_kernel(
        const float* __restrict__ conv_w,
        const float* __restrict__ conv_b) {
    __shared__ float s_tile[2 * HTH * HTWP];   // 13.4 KB
    __shared__ float s_w[98];

    int tx  = threadIdx.x;              // 0..27
    int ty  = threadIdx.y;              // 0..7
    int tid = ty * 28 + tx;             // 0..223

    int w0 = blockIdx.x * CTW;          // 2
    int h0 = blockIdx.y * CTH;          // 28
    int b  = blockIdx.z;                // 16

    if (tid < 98) s_w[tid] = conv_w[tid];

    // halo load: 2 * 14 * 118 = 3304 elements (L2-hot feat from reduce)
    const float* srcA = g_avg + b * HW_;
    const float* srcM = g_max + b * HW_;
    for (int i = tid; i < 2 * HTH * HTW; i += 224) {
        int ch = i / (HTH * HTW);
        int rr = i - ch * (HTH * HTW);
        int r  = rr / HTW;
        int cc = rr - r * HTW;
        int gh = h0 + r - 3;
        int gw = w0 + cc - 3;
        float v = 0.f;
        if (gh >= 0 && gh < H_ && gw >= 0 && gw < W_)
            v = __ldg((ch == 0 ? srcA : srcM) + gh * W_ + gw);
        s_tile[ch * HTH * HTWP + r * HTWP + cc] = v;
    }
    __syncthreads();

    float acc0 = conv_b[0], acc1 = acc0, acc2 = acc0, acc3 = acc0;

#pragma unroll
    for (int ch = 0; ch < 2; ch++) {
#pragma unroll
        for (int kh = 0; kh < 7; kh++) {
            const float* rp = s_tile + ch * HTH * HTWP + (ty + kh) * HTWP + 4 * tx;
            float4 v0 = *(const float4*)(rp);        // LDS.128 aligned
            float4 v1 = *(const float4*)(rp + 4);
            float  e0 = rp[8];
            float  e1 = rp[9];
            float r_[10] = { v0.x, v0.y, v0.z, v0.w,
                             v1.x, v1.y, v1.z, v1.w, e0, e1 };
            const float* wk = s_w + ch * 49 + kh * 7;
#pragma unroll
            for (int kw = 0; kw < 7; kw++) {
                float wv = wk[kw];
                acc0 = fmaf(r_[kw + 0], wv, acc0);
                acc1 = fmaf(r_[kw + 1], wv, acc1);
                acc2 = fmaf(r_[kw + 2], wv, acc2);
                acc3 = fmaf(r_[kw + 3], wv, acc3);
            }
        }
    }

    float4 gate;
    gate.x = 1.0f / (1.0f + __expf(-acc0));
    gate.y = 1.0f / (1.0f + __expf(-acc1));
    gate.z = 1.0f / (1.0f + __expf(-acc2));
    gate.w = 1.0f / (1.0f + __expf(-acc3));

    int out_idx = b * HW_ + (h0 + ty) * W_ + w0 + 4 * tx;   // 16B aligned
    __stcs((float4*)(g_gate + out_idx), gate);
}

// ---------------------------------------------------------------------------
// Kernel 3: out = x * gate, block-REVERSED order. Reduce streamed x in
// ascending order, so L2 holds the tail of x at handoff; first-scheduled
// (low blockIdx) CTAs here read that hot tail -> partial L2 hits.
// Coalescing preserved (reversal at block granularity).
// ---------------------------------------------------------------------------
__global__ void gate_mul_kernel(const float* __restrict__ x,
                                float* __restrict__ out) {
    int blk  = gridDim.x - 1 - blockIdx.x;
    int idx4 = blk * blockDim.x + threadIdx.x;
    if (idx4 >= TOTAL4) return;

    int b   = idx4 / CHW4_;
    int r   = idx4 - b * CHW4_;
    int hw4 = r % HW4_;

    float4 g = ((const float4*)g_gate)[b * HW4_ + hw4];
    float4 v = ((const float4*)x)[idx4];
    v.x *= g.x; v.y *= g.y; v.z *= g.z; v.w *= g.w;
    __stcs(((float4*)out) + idx4, v);
}

// ---------------------------------------------------------------------------
extern "C" void kernel_launch(void* const* d_in, const int* in_sizes, int n_in,
                              void* d_out, int out_size) {
    const float* x      = (const float*)d_in[0];
    const float* conv_w = (const float*)d_in[1];
    const float* conv_b = (const float*)d_in[2];
    float* out = (float*)d_out;

    // K1: channel reduce over full tensor (at DRAM roofline)
    {
        int n = B_ * HW4_;                   // 200704 threads
        reduce_kernel<<<(n + 255) / 256, 256>>>(x);
    }
    // K2: conv + sigmoid -> gate (small, L2-bound)
    {
        dim3 blk(28, 8);
        dim3 grd(W_ / CTW, H_ / CTH, B_);    // 2 x 28 x 16 = 896 CTAs
        conv_sigmoid_kernel<<<grd, blk>>>(conv_w, conv_b);
    }
    // K3: broadcast multiply, reversed for L2 tail reuse
    {
        int nblk = (TOTAL4 + 255) / 256;     // 50176
        gate_mul_kernel<<<nblk, 256>>>(x, out);
    }
}